// round 4
// baseline (speedup 1.0000x reference)
#include <cuda_runtime.h>
#include <cuda_fp16.h>
#include <cstdint>

#define MAX_NODES 100000
#define MAX_EDGES 800000
#define F_DIM     16
#define K_DIM     16
#define OUT_SCALE (1.0f / 128.0f)

// Yh[k][n][16] fp16 (51.2 MB): stage1 stores coalesce; stage2 reads 4 blocks.
__device__ __half g_Yh[(size_t)K_DIM * MAX_NODES * 16];
// Counting-sort state
__device__ int   g_cnt[MAX_NODES];
__device__ int   g_cur[MAX_NODES];
__device__ int   g_total;
__device__ uint4 g_rec[MAX_EDGES];   // {dj, di|k00<<20, s(f32 bits), t(f32 bits)}

// ---------- packed fp32x2 helpers ----------
__device__ __forceinline__ unsigned long long pack2(float a, float b) {
    unsigned long long r;
    asm("mov.b64 %0, {%1, %2};" : "=l"(r) : "f"(a), "f"(b));
    return r;
}
__device__ __forceinline__ void fma2(unsigned long long& d,
                                     unsigned long long a,
                                     unsigned long long b) {
    asm("fma.rn.f32x2 %0, %1, %2, %3;" : "=l"(d) : "l"(a), "l"(b), "l"(d));
}
__device__ __forceinline__ void unpack2(unsigned long long v, float& a, float& b) {
    asm("mov.b64 {%0, %1}, %2;" : "=f"(a), "=f"(b) : "l"(v));
}
__device__ __forceinline__ unsigned h2pack(float lo, float hi) {
    __half2 h = __floats2half2_rn(lo, hi);
    return *reinterpret_cast<unsigned*>(&h);
}
__device__ __forceinline__ float2 h2f(unsigned u) {
    __half2 h = *reinterpret_cast<__half2*>(&u);
    return __half22float2(h);
}

// ============================================================================
// Stage 1: Yh[k][n][:] = x[n] @ W[k]   (unchanged from R3)
// ============================================================================
__global__ __launch_bounds__(256)
void stage1_kernel(const float* __restrict__ x,
                   const float* __restrict__ W,
                   int n_nodes) {
    __shared__ float Ws[4096];
    for (int idx = threadIdx.x; idx < 4096; idx += 256)
        Ws[idx] = W[idx];
    __syncthreads();

    int node = blockIdx.x * 256 + threadIdx.x;
    if (node >= n_nodes) return;

    unsigned long long x2[16];
    const float4* xp = reinterpret_cast<const float4*>(x + (size_t)node * F_DIM);
#pragma unroll
    for (int q = 0; q < 4; q++) {
        float4 v = xp[q];
        x2[4 * q + 0] = pack2(v.x, v.x);
        x2[4 * q + 1] = pack2(v.y, v.y);
        x2[4 * q + 2] = pack2(v.z, v.z);
        x2[4 * q + 3] = pack2(v.w, v.w);
    }

#pragma unroll 1
    for (int k = 0; k < K_DIM; k++) {
        unsigned long long acc0 = 0ull, acc1 = 0ull, acc2 = 0ull, acc3 = 0ull;
        unsigned long long acc4 = 0ull, acc5 = 0ull, acc6 = 0ull, acc7 = 0ull;
        const ulonglong2* wbase =
            reinterpret_cast<const ulonglong2*>(Ws + k * 256);
#pragma unroll
        for (int i = 0; i < F_DIM; i++) {
            ulonglong2 wa = wbase[i * 4 + 0];
            ulonglong2 wb = wbase[i * 4 + 1];
            ulonglong2 wc = wbase[i * 4 + 2];
            ulonglong2 wd = wbase[i * 4 + 3];
            unsigned long long xi = x2[i];
            fma2(acc0, xi, wa.x);
            fma2(acc1, xi, wa.y);
            fma2(acc2, xi, wb.x);
            fma2(acc3, xi, wb.y);
            fma2(acc4, xi, wc.x);
            fma2(acc5, xi, wc.y);
            fma2(acc6, xi, wd.x);
            fma2(acc7, xi, wd.y);
        }
        float o0, o1, o2, o3, o4, o5, o6, o7;
        float o8, o9, oa, ob, oc, od, oe, of_;
        unpack2(acc0, o0, o1); unpack2(acc1, o2, o3);
        unpack2(acc2, o4, o5); unpack2(acc3, o6, o7);
        unpack2(acc4, o8, o9); unpack2(acc5, oa, ob);
        unpack2(acc6, oc, od); unpack2(acc7, oe, of_);

        uint4 s0, s1;
        s0.x = h2pack(o0, o1); s0.y = h2pack(o2, o3);
        s0.z = h2pack(o4, o5); s0.w = h2pack(o6, o7);
        s1.x = h2pack(o8, o9); s1.y = h2pack(oa, ob);
        s1.z = h2pack(oc, od); s1.w = h2pack(oe, of_);

        uint4* yo = reinterpret_cast<uint4*>(
            g_Yh + ((size_t)k * n_nodes + node) * 16);
        yo[0] = s0;
        yo[1] = s1;
    }
}

// ============================================================================
// Sort pass A: histogram of dj (masked edges skipped)
// ============================================================================
__global__ __launch_bounds__(256)
void k_hist(const int* __restrict__ ei, const int* __restrict__ ej, int n_edges) {
    int e = blockIdx.x * 256 + threadIdx.x;
    if (e >= n_edges) return;
    int di = ei[e], dj = ej[e];
    if (di != dj) atomicAdd(&g_cnt[dj], 1);
}

// ============================================================================
// Sort pass B: exclusive scan of g_cnt -> g_cur (single block, strip per thread)
// ============================================================================
__global__ __launch_bounds__(1024)
void k_scan(int n_nodes) {
    __shared__ int sp[1024];
    int t = threadIdx.x;
    int strip = (n_nodes + 1023) / 1024;
    int lo = t * strip;
    int hi = min(lo + strip, n_nodes);

    int sum = 0;
    for (int i = lo; i < hi; i++) sum += g_cnt[i];
    sp[t] = sum;
    __syncthreads();

    // inclusive Hillis-Steele scan
#pragma unroll
    for (int d = 1; d < 1024; d <<= 1) {
        int v = (t >= d) ? sp[t - d] : 0;
        __syncthreads();
        sp[t] += v;
        __syncthreads();
    }

    int run = (t == 0) ? 0 : sp[t - 1];
    if (t == 1023) g_total = sp[1023];
    for (int i = lo; i < hi; i++) {
        int c = g_cnt[i];
        g_cur[i] = run;
        run += c;
    }
}

// ============================================================================
// Sort pass C: scatter packed edge records into dj-sorted order.
// Also precomputes the bilinear-cell decomposition (a,b,s,t).
// ============================================================================
__global__ __launch_bounds__(256)
void k_scatter(const float2* __restrict__ edge_attr,
               const int* __restrict__ ei, const int* __restrict__ ej,
               int n_edges) {
    int e = blockIdx.x * 256 + threadIdx.x;
    if (e >= n_edges) return;
    int di = ei[e], dj = ej[e];
    if (di == dj) return;

    float2 at = edge_attr[e];
    float ux = fminf(fmaxf(at.x, -1.0f), 1.0f);
    float uy = fminf(fmaxf(at.y, -1.0f), 1.0f);
    float vx = (ux + 1.0f) * 1.5f;
    float vy = (uy + 1.0f) * 1.5f;
    int a = min((int)vx, 2);
    int b = min((int)vy, 2);
    float s = vx - (float)a;
    float t = vy - (float)b;
    int k00 = a * 4 + b;

    int pos = atomicAdd(&g_cur[dj], 1);
    g_rec[pos] = make_uint4((unsigned)dj,
                            (unsigned)(di | (k00 << 20)),
                            __float_as_uint(s),
                            __float_as_uint(t));
}

// ============================================================================
// Stage 2 (sorted): consecutive threads share dj -> coalesced/broadcast gather
// ============================================================================
__global__ __launch_bounds__(256)
void stage2_sorted(float* __restrict__ out, int n_nodes, int n_edges) {
    int e = blockIdx.x * 256 + threadIdx.x;
    if (e >= g_total) return;

    uint4 r = g_rec[e];
    int dj  = (int)r.x;
    int dik = (int)r.y;
    int di  = dik & 0xFFFFF;
    int k00 = dik >> 20;
    float s = __uint_as_float(r.z);
    float t = __uint_as_float(r.w);

    float c00 = (1.0f - s) * (1.0f - t) * OUT_SCALE;
    float c01 = (1.0f - s) * t * OUT_SCALE;
    float c10 = s * (1.0f - t) * OUT_SCALE;
    float c11 = s * t * OUT_SCALE;

    size_t row = (size_t)dj * 16;
    size_t kstride = (size_t)n_nodes * 16;
    const uint4* pA = reinterpret_cast<const uint4*>(g_Yh + (size_t)k00 * kstride + row);
    const uint4* pB = reinterpret_cast<const uint4*>(g_Yh + (size_t)(k00 + 1) * kstride + row);
    const uint4* pC = reinterpret_cast<const uint4*>(g_Yh + (size_t)(k00 + 4) * kstride + row);
    const uint4* pD = reinterpret_cast<const uint4*>(g_Yh + (size_t)(k00 + 5) * kstride + row);

    uint4 A0 = pA[0], A1 = pA[1];
    uint4 B0 = pB[0], B1 = pB[1];
    uint4 C0 = pC[0], C1 = pC[1];
    uint4 D0 = pD[0], D1 = pD[1];

    float* obase = out + (size_t)di * 16;

    {
        float2 fA, fB, fC, fD, m01, m23, m45, m67;
        fA = h2f(A0.x); fB = h2f(B0.x); fC = h2f(C0.x); fD = h2f(D0.x);
        m01.x = c00*fA.x + c01*fB.x + c10*fC.x + c11*fD.x;
        m01.y = c00*fA.y + c01*fB.y + c10*fC.y + c11*fD.y;
        fA = h2f(A0.y); fB = h2f(B0.y); fC = h2f(C0.y); fD = h2f(D0.y);
        m23.x = c00*fA.x + c01*fB.x + c10*fC.x + c11*fD.x;
        m23.y = c00*fA.y + c01*fB.y + c10*fC.y + c11*fD.y;
        fA = h2f(A0.z); fB = h2f(B0.z); fC = h2f(C0.z); fD = h2f(D0.z);
        m45.x = c00*fA.x + c01*fB.x + c10*fC.x + c11*fD.x;
        m45.y = c00*fA.y + c01*fB.y + c10*fC.y + c11*fD.y;
        fA = h2f(A0.w); fB = h2f(B0.w); fC = h2f(C0.w); fD = h2f(D0.w);
        m67.x = c00*fA.x + c01*fB.x + c10*fC.x + c11*fD.x;
        m67.y = c00*fA.y + c01*fB.y + c10*fC.y + c11*fD.y;
        asm volatile("red.global.add.v4.f32 [%0], {%1, %2, %3, %4};"
                     :: "l"(obase + 0), "f"(m01.x), "f"(m01.y), "f"(m23.x), "f"(m23.y)
                     : "memory");
        asm volatile("red.global.add.v4.f32 [%0], {%1, %2, %3, %4};"
                     :: "l"(obase + 4), "f"(m45.x), "f"(m45.y), "f"(m67.x), "f"(m67.y)
                     : "memory");
    }
    {
        float2 fA, fB, fC, fD, m01, m23, m45, m67;
        fA = h2f(A1.x); fB = h2f(B1.x); fC = h2f(C1.x); fD = h2f(D1.x);
        m01.x = c00*fA.x + c01*fB.x + c10*fC.x + c11*fD.x;
        m01.y = c00*fA.y + c01*fB.y + c10*fC.y + c11*fD.y;
        fA = h2f(A1.y); fB = h2f(B1.y); fC = h2f(C1.y); fD = h2f(D1.y);
        m23.x = c00*fA.x + c01*fB.x + c10*fC.x + c11*fD.x;
        m23.y = c00*fA.y + c01*fB.y + c10*fC.y + c11*fD.y;
        fA = h2f(A1.z); fB = h2f(B1.z); fC = h2f(C1.z); fD = h2f(D1.z);
        m45.x = c00*fA.x + c01*fB.x + c10*fC.x + c11*fD.x;
        m45.y = c00*fA.y + c01*fB.y + c10*fC.y + c11*fD.y;
        fA = h2f(A1.w); fB = h2f(B1.w); fC = h2f(C1.w); fD = h2f(D1.w);
        m67.x = c00*fA.x + c01*fB.x + c10*fC.x + c11*fD.x;
        m67.y = c00*fA.y + c01*fB.y + c10*fC.y + c11*fD.y;
        asm volatile("red.global.add.v4.f32 [%0], {%1, %2, %3, %4};"
                     :: "l"(obase + 8), "f"(m01.x), "f"(m01.y), "f"(m23.x), "f"(m23.y)
                     : "memory");
        asm volatile("red.global.add.v4.f32 [%0], {%1, %2, %3, %4};"
                     :: "l"(obase + 12), "f"(m45.x), "f"(m45.y), "f"(m67.x), "f"(m67.y)
                     : "memory");
    }
}

extern "C" void kernel_launch(void* const* d_in, const int* in_sizes, int n_in,
                              void* d_out, int out_size) {
    const float*  x  = (const float*)d_in[0];
    const float2* ea = (const float2*)d_in[1];
    const float*  W  = (const float*)d_in[2];
    const int*    ei = (const int*)d_in[3];
    const int*    ej = (const int*)d_in[4];
    float* out = (float*)d_out;

    int n_nodes = in_sizes[0] / F_DIM;
    int n_edges = in_sizes[1] / 2;

    void* cnt_ptr = nullptr;
    cudaGetSymbolAddress(&cnt_ptr, g_cnt);

    cudaMemsetAsync(d_out, 0, (size_t)out_size * sizeof(float), 0);
    cudaMemsetAsync(cnt_ptr, 0, (size_t)n_nodes * sizeof(int), 0);

    int eb = (n_edges + 255) / 256;
    k_hist   <<<eb, 256>>>(ei, ej, n_edges);
    k_scan   <<<1, 1024>>>(n_nodes);
    k_scatter<<<eb, 256>>>(ea, ei, ej, n_edges);

    stage1_kernel<<<(n_nodes + 255) / 256, 256>>>(x, W, n_nodes);
    stage2_sorted<<<eb, 256>>>(out, n_nodes, n_edges);
}